// round 2
// baseline (speedup 1.0000x reference)
#include <cuda_runtime.h>
#include <math.h>

// GreenTF as an exponentially-windowed complex IIR filter bank.
//   z[n]   = sum_{m>=0} wav[n-m] * alpha^m,  alpha = 2^(-1/320) * cis(2*pi*f/16000)
//   S[f,t] = z[16t] - alpha^2048 * z[16(t-128)]          (exact truncation correction)
//   sspec  = Im(S)*SC, cspec = Re(S)*SC
// t-chunked: 10 chunks of 200 outputs; each chunk warms up 128 steps from zero
// state. Because 2048 = 16*128, the ring difference cancels the missing
// pre-history EXACTLY, so chunking introduces no approximation error.
// Tap sums use packed fma.rn.f32x2 (2 MACs/instr).

#define NFREQ   8001
#define NCHAIN  (2 * NFREQ)
#define TOUT    2000
#define TWAV    32000
#define SR_I    16000
#define CHUNK   200
#define NCHUNK  10
#define WARM    128

static __device__ __forceinline__ unsigned long long pk2(float x, float y) {
    unsigned long long r;
    asm("mov.b64 %0, {%1,%2};" : "=l"(r) : "f"(x), "f"(y));
    return r;
}
static __device__ __forceinline__ float2 upk2(unsigned long long v) {
    float2 r;
    asm("mov.b64 {%0,%1}, %2;" : "=f"(r.x), "=f"(r.y) : "l"(v));
    return r;
}
static __device__ __forceinline__ unsigned long long ffma2_(
    unsigned long long a, unsigned long long b, unsigned long long c) {
    unsigned long long d;
    asm("fma.rn.f32x2 %0, %1, %2, %3;" : "=l"(d) : "l"(a), "l"(b), "l"(c));
    return d;
}
static __device__ __forceinline__ unsigned long long fmul2_(
    unsigned long long a, unsigned long long b) {
    unsigned long long d;
    asm("mul.rn.f32x2 %0, %1, %2;" : "=l"(d) : "l"(a), "l"(b));
    return d;
}

__global__ void __launch_bounds__(128, 1)
greentf_kernel(const float* __restrict__ wav, float* __restrict__ out)
{
    int gid = blockIdx.x * 128 + threadIdx.x;
    if (gid >= NCHAIN) return;
    int chunk = blockIdx.y;
    int b = gid / NFREQ;
    int f = gid - b * NFREQ;
    const float* __restrict__ w = wav + b * TWAV;

    const float TW = 6.283185307179586f / 16000.0f;

    // d_j = alpha^{-j}, j=0..15 (j=0 slot zeroed: cur[0] enters recurrence directly)
    float djr[16], dji[16];
    djr[0] = 0.f; dji[0] = 0.f;
#pragma unroll
    for (int j = 1; j < 16; ++j) {
        int ph = (f * j) % SR_I;
        float s, c;
        sincosf(TW * (float)ph, &s, &c);
        float g = exp2f((float)j * (1.0f / 320.0f));   // rho^{-j}
        djr[j] = c * g;
        dji[j] = -s * g;
    }
    unsigned long long dR2[8], dI2[8];
#pragma unroll
    for (int p = 0; p < 8; ++p) {
        dR2[p] = pk2(djr[2 * p], djr[2 * p + 1]);
        dI2[p] = pk2(dji[2 * p], dji[2 * p + 1]);
    }

    // alpha^16
    float A16r, A16i;
    {
        int ph = (16 * f) % SR_I;
        float s, c;
        sincosf(TW * (float)ph, &s, &c);
        float d = exp2f(-16.0f / 320.0f);
        A16r = c * d; A16i = s * d;
    }
    // alpha^2048
    float A2r, A2i;
    {
        int ph = (2048 * f) % SR_I;
        float s, c;
        sincosf(TW * (float)ph, &s, &c);
        float d = exp2f(-2048.0f / 320.0f);
        A2r = c * d; A2i = s * d;
    }
    // SC = sqrt(8) / sum_{m=0}^{2047} rho^m
    double rho = exp2(-1.0 / 320.0);
    double geo = (1.0 - exp2(-2048.0 / 320.0)) / (1.0 - rho);
    const float SC = (float)(2.8284271247461903 / geo);

    float rr = 0.f, ri = 0.f, Gr = 0.f, Gi = 0.f;
    float2 ring[128];

    const int t0 = chunk * CHUNK;

    if (chunk == 0) {
#pragma unroll
        for (int i = 0; i < 128; ++i) ring[i] = make_float2(0.f, 0.f);
    } else {
        // 128 warm-up steps: recurrence + ring fill, no output.
        for (int t = t0 - WARM; t < t0; ++t) {
            const ulonglong2* p = (const ulonglong2*)(w + 16 * t);
            ulonglong2 u0 = p[0], u1 = p[1], u2 = p[2], u3 = p[3];
            unsigned long long c2[8] = { u0.x, u0.y, u1.x, u1.y,
                                         u2.x, u2.y, u3.x, u3.y };
            float cur0 = upk2(c2[0]).x;
            // r[t] = A16*(r[t-1] + G_{t-1}) + cur0
            float tr = rr + Gr, ti = ri + Gi;
            rr = fmaf(A16r, tr, fmaf(-A16i, ti, cur0));
            ri = fmaf(A16i, tr, A16r * ti);
            // new G from this block (used next step)
            unsigned long long aR = fmul2_(c2[0], dR2[0]);
            unsigned long long aI = fmul2_(c2[0], dI2[0]);
#pragma unroll
            for (int q = 1; q < 8; ++q) {
                aR = ffma2_(c2[q], dR2[q], aR);
                aI = ffma2_(c2[q], dI2[q], aI);
            }
            float2 ar = upk2(aR), ai = upk2(aI);
            Gr = ar.x + ar.y;
            Gi = ai.x + ai.y;
            ring[t & 127] = make_float2(rr, ri);
        }
    }

    float* __restrict__ outs = out + (size_t)gid * TOUT + t0;
    float* __restrict__ outc = out + (size_t)NCHAIN * TOUT + (size_t)gid * TOUT + t0;

    for (int q0 = 0; q0 < CHUNK; q0 += 4) {
        float obs[4], obc[4];
#pragma unroll
        for (int u = 0; u < 4; ++u) {
            int t = t0 + q0 + u;
            const ulonglong2* p = (const ulonglong2*)(w + 16 * t);
            ulonglong2 u0 = p[0], u1 = p[1], u2 = p[2], u3 = p[3];
            unsigned long long c2[8] = { u0.x, u0.y, u1.x, u1.y,
                                         u2.x, u2.y, u3.x, u3.y };
            float cur0 = upk2(c2[0]).x;
            float tr = rr + Gr, ti = ri + Gi;
            rr = fmaf(A16r, tr, fmaf(-A16i, ti, cur0));
            ri = fmaf(A16i, tr, A16r * ti);
            unsigned long long aR = fmul2_(c2[0], dR2[0]);
            unsigned long long aI = fmul2_(c2[0], dI2[0]);
#pragma unroll
            for (int q = 1; q < 8; ++q) {
                aR = ffma2_(c2[q], dR2[q], aR);
                aI = ffma2_(c2[q], dI2[q], aI);
            }
            float2 ar = upk2(aR), ai = upk2(aI);
            Gr = ar.x + ar.y;
            Gi = ai.x + ai.y;

            // S[t] = r[t] - alpha^2048 * r[t-128]
            int idx = t & 127;
            float2 h = ring[idx];
            ring[idx] = make_float2(rr, ri);
            float Sr = fmaf(-A2r, h.x, fmaf( A2i, h.y, rr));
            float Si = fmaf(-A2i, h.x, fmaf(-A2r, h.y, ri));
            obs[u] = Si * SC;
            obc[u] = Sr * SC;
        }
        *(float4*)(outs + q0) = make_float4(obs[0], obs[1], obs[2], obs[3]);
        *(float4*)(outc + q0) = make_float4(obc[0], obc[1], obc[2], obc[3]);
    }
}

extern "C" void kernel_launch(void* const* d_in, const int* in_sizes, int n_in,
                              void* d_out, int out_size)
{
    (void)in_sizes; (void)n_in; (void)out_size;
    const float* wav = (const float*)d_in[0];   // (2, 32000) fp32
    float* out = (float*)d_out;                 // sspec then cspec, fp32
    dim3 grid((NCHAIN + 127) / 128, NCHUNK, 1); // 126 x 10
    greentf_kernel<<<grid, 128>>>(wav, out);
}

// round 3
// speedup vs baseline: 1.6803x; 1.6803x over previous
#include <cuda_runtime.h>
#include <cuda_fp16.h>
#include <math.h>

// GreenTF as an exponentially-windowed complex IIR filter bank.
//   z[n]   = sum_{m>=0} wav[n-m] * alpha^m,  alpha = 2^(-1/320) * cis(2*pi*f/16000)
//   S[f,t] = z[16t] - alpha^2048 * z[16(t-128)]       (exact truncation correction)
//   sspec  = Im(S)*SC, cspec = Re(S)*SC
// t-chunked (10 x 200 outputs) with 128-step exact warm-up (2048 = 16*128 makes
// the ring difference cancel missing pre-history exactly).
// r[t-128] history lives in SHARED memory as half2 (correction is scaled by
// |alpha^2048| = 0.0118, so fp16 rounding contributes <3e-6 relative error).
// Per-thread private smem column -> no bank conflicts, no __syncthreads.

#define NFREQ   8001
#define NCHAIN  (2 * NFREQ)
#define TOUT    2000
#define TWAV    32000
#define SR_I    16000
#define CHUNK   200
#define NCHUNK  10
#define WARM    128
#define BLOCK   128

static __device__ __forceinline__ unsigned long long pk2(float x, float y) {
    unsigned long long r;
    asm("mov.b64 %0, {%1,%2};" : "=l"(r) : "f"(x), "f"(y));
    return r;
}
static __device__ __forceinline__ float2 upk2(unsigned long long v) {
    float2 r;
    asm("mov.b64 {%0,%1}, %2;" : "=f"(r.x), "=f"(r.y) : "l"(v));
    return r;
}
static __device__ __forceinline__ unsigned long long ffma2_(
    unsigned long long a, unsigned long long b, unsigned long long c) {
    unsigned long long d;
    asm("fma.rn.f32x2 %0, %1, %2, %3;" : "=l"(d) : "l"(a), "l"(b), "l"(c));
    return d;
}
static __device__ __forceinline__ unsigned long long fmul2_(
    unsigned long long a, unsigned long long b) {
    unsigned long long d;
    asm("mul.rn.f32x2 %0, %1, %2;" : "=l"(d) : "l"(a), "l"(b));
    return d;
}

extern __shared__ __half2 s_ring[];   // [WARM][BLOCK] : 128*128*4B = 64 KB

__global__ void __launch_bounds__(BLOCK, 3)
greentf_kernel(const float* __restrict__ wav, float* __restrict__ out)
{
    const int tid = threadIdx.x;
    int gid = blockIdx.x * BLOCK + tid;
    if (gid >= NCHAIN) return;
    const int chunk = blockIdx.y;
    const int b = gid / NFREQ;
    const int f = gid - b * NFREQ;
    const float* __restrict__ w = wav + b * TWAV;

    const float TW = 6.283185307179586f / 16000.0f;

    // d_j = alpha^{-j}, j=1..15 (slot 0 zeroed; cur[0] enters recurrence directly)
    float djr[16], dji[16];
    djr[0] = 0.f; dji[0] = 0.f;
#pragma unroll
    for (int j = 1; j < 16; ++j) {
        int ph = (f * j) % SR_I;
        float s, c;
        sincosf(TW * (float)ph, &s, &c);
        float g = exp2f((float)j * (1.0f / 320.0f));   // rho^{-j}
        djr[j] = c * g;
        dji[j] = -s * g;
    }
    unsigned long long dR2[8], dI2[8];
#pragma unroll
    for (int p = 0; p < 8; ++p) {
        dR2[p] = pk2(djr[2 * p], djr[2 * p + 1]);
        dI2[p] = pk2(dji[2 * p], dji[2 * p + 1]);
    }

    // alpha^16
    float A16r, A16i;
    {
        int ph = (16 * f) % SR_I;
        float s, c;
        sincosf(TW * (float)ph, &s, &c);
        float d = exp2f(-16.0f / 320.0f);
        A16r = c * d; A16i = s * d;
    }
    // alpha^2048
    float A2r, A2i;
    {
        int ph = (2048 * f) % SR_I;
        float s, c;
        sincosf(TW * (float)ph, &s, &c);
        float d = exp2f(-2048.0f / 320.0f);
        A2r = c * d; A2i = s * d;
    }
    // SC = sqrt(8) / sum_{m=0}^{2047} rho^m
    double rho = exp2(-1.0 / 320.0);
    double geo = (1.0 - exp2(-2048.0 / 320.0)) / (1.0 - rho);
    const float SC = (float)(2.8284271247461903 / geo);

    float rr = 0.f, ri = 0.f, Gr = 0.f, Gi = 0.f;
    const int t0 = chunk * CHUNK;

    if (chunk == 0) {
#pragma unroll 8
        for (int i = 0; i < WARM; ++i)
            s_ring[i * BLOCK + tid] = __half2half2(__float2half_rn(0.f));
    } else {
        // 128 warm-up steps: recurrence + ring fill, no output.
        for (int t = t0 - WARM; t < t0; ++t) {
            const ulonglong2* p = (const ulonglong2*)(w + 16 * t);
            ulonglong2 u0 = p[0], u1 = p[1], u2 = p[2], u3 = p[3];
            unsigned long long c2[8] = { u0.x, u0.y, u1.x, u1.y,
                                         u2.x, u2.y, u3.x, u3.y };
            float cur0 = upk2(c2[0]).x;
            float tr = rr + Gr, ti = ri + Gi;
            rr = fmaf(A16r, tr, fmaf(-A16i, ti, cur0));
            ri = fmaf(A16i, tr, A16r * ti);
            unsigned long long aR = fmul2_(c2[0], dR2[0]);
            unsigned long long aI = fmul2_(c2[0], dI2[0]);
#pragma unroll
            for (int q = 1; q < 8; ++q) {
                aR = ffma2_(c2[q], dR2[q], aR);
                aI = ffma2_(c2[q], dI2[q], aI);
            }
            float2 ar = upk2(aR), ai = upk2(aI);
            Gr = ar.x + ar.y;
            Gi = ai.x + ai.y;
            s_ring[(t & (WARM - 1)) * BLOCK + tid] =
                __floats2half2_rn(rr * SC, ri * SC);
        }
    }

    float* __restrict__ outs = out + (size_t)gid * TOUT + t0;
    float* __restrict__ outc = out + (size_t)NCHAIN * TOUT + (size_t)gid * TOUT + t0;

    for (int q0 = 0; q0 < CHUNK; q0 += 4) {
        float obs[4], obc[4];
#pragma unroll
        for (int u = 0; u < 4; ++u) {
            int t = t0 + q0 + u;
            const ulonglong2* p = (const ulonglong2*)(w + 16 * t);
            ulonglong2 u0 = p[0], u1 = p[1], u2 = p[2], u3 = p[3];
            unsigned long long c2[8] = { u0.x, u0.y, u1.x, u1.y,
                                         u2.x, u2.y, u3.x, u3.y };
            float cur0 = upk2(c2[0]).x;
            float tr = rr + Gr, ti = ri + Gi;
            rr = fmaf(A16r, tr, fmaf(-A16i, ti, cur0));
            ri = fmaf(A16i, tr, A16r * ti);
            unsigned long long aR = fmul2_(c2[0], dR2[0]);
            unsigned long long aI = fmul2_(c2[0], dI2[0]);
#pragma unroll
            for (int q = 1; q < 8; ++q) {
                aR = ffma2_(c2[q], dR2[q], aR);
                aI = ffma2_(c2[q], dI2[q], aI);
            }
            float2 ar = upk2(aR), ai = upk2(aI);
            Gr = ar.x + ar.y;
            Gi = ai.x + ai.y;

            // scaled r for output & ring
            float sr = rr * SC, si = ri * SC;

            // S*SC = sr - alpha^2048 * (ring value, already scaled)
            int slot = (t & (WARM - 1)) * BLOCK + tid;
            float2 h = __half22float2(s_ring[slot]);
            s_ring[slot] = __floats2half2_rn(sr, si);
            float Sr = fmaf(-A2r, h.x, fmaf( A2i, h.y, sr));
            float Si = fmaf(-A2i, h.x, fmaf(-A2r, h.y, si));
            obs[u] = Si;
            obc[u] = Sr;
        }
        *(float4*)(outs + q0) = make_float4(obs[0], obs[1], obs[2], obs[3]);
        *(float4*)(outc + q0) = make_float4(obc[0], obc[1], obc[2], obc[3]);
    }
}

extern "C" void kernel_launch(void* const* d_in, const int* in_sizes, int n_in,
                              void* d_out, int out_size)
{
    (void)in_sizes; (void)n_in; (void)out_size;
    const float* wav = (const float*)d_in[0];   // (2, 32000) fp32
    float* out = (float*)d_out;                 // sspec then cspec, fp32

    static const int smem_bytes = WARM * BLOCK * (int)sizeof(__half2); // 64 KB
    cudaFuncSetAttribute(greentf_kernel,
                         cudaFuncAttributeMaxDynamicSharedMemorySize, smem_bytes);

    dim3 grid((NCHAIN + BLOCK - 1) / BLOCK, NCHUNK, 1);   // 126 x 10
    greentf_kernel<<<grid, BLOCK, smem_bytes>>>(wav, out);
}

// round 4
// speedup vs baseline: 1.6967x; 1.0098x over previous
#include <cuda_runtime.h>
#include <cuda_fp16.h>
#include <math.h>

// GreenTF as an exponentially-windowed complex IIR filter bank.
//   z[n]   = sum_{m>=0} wav[n-m] * alpha^m,  alpha = 2^(-1/320) * cis(2*pi*f/16000)
//   S[f,t] = z[16t] - alpha^2048 * z[16(t-128)]       (exact truncation correction)
//   sspec  = Im(S)*SC, cspec = Re(S)*SC
// t-chunked (7 chunks: 6x288 + 272) with 128-step exact warm-up (2048 = 16*128
// makes the ring difference cancel the missing pre-history exactly).
// 882 CTAs = 1.99 clean waves at 3 CTAs/SM.
// r[t-128] history in shared memory as half2 (correction scaled by 0.0118 ->
// fp16 rounding contributes <3e-6). SC pre-folded into tap coefficients.
// 4-step groups batch all ring LDS + wav LDG up front for MLP.

#define NFREQ   8001
#define NCHAIN  (2 * NFREQ)
#define TOUT    2000
#define TWAV    32000
#define SR_I    16000
#define CHUNK   288
#define NCHUNK  7
#define WARM    128
#define BLOCK   128

static __device__ __forceinline__ unsigned long long pk2(float x, float y) {
    unsigned long long r;
    asm("mov.b64 %0, {%1,%2};" : "=l"(r) : "f"(x), "f"(y));
    return r;
}
static __device__ __forceinline__ float2 upk2(unsigned long long v) {
    float2 r;
    asm("mov.b64 {%0,%1}, %2;" : "=f"(r.x), "=f"(r.y) : "l"(v));
    return r;
}
static __device__ __forceinline__ unsigned long long ffma2_(
    unsigned long long a, unsigned long long b, unsigned long long c) {
    unsigned long long d;
    asm("fma.rn.f32x2 %0, %1, %2, %3;" : "=l"(d) : "l"(a), "l"(b), "l"(c));
    return d;
}
static __device__ __forceinline__ unsigned long long fmul2_(
    unsigned long long a, unsigned long long b) {
    unsigned long long d;
    asm("mul.rn.f32x2 %0, %1, %2;" : "=l"(d) : "l"(a), "l"(b));
    return d;
}

extern __shared__ __half2 s_ring[];   // [WARM][BLOCK] : 128*128*4B = 64 KB

__global__ void __launch_bounds__(BLOCK, 3)
greentf_kernel(const float* __restrict__ wav, float* __restrict__ out)
{
    const int tid = threadIdx.x;
    int gid = blockIdx.x * BLOCK + tid;
    if (gid >= NCHAIN) return;
    const int chunk = blockIdx.y;
    const int b = gid / NFREQ;
    const int f = gid - b * NFREQ;
    const float* __restrict__ w = wav + b * TWAV;

    const float TW = 6.283185307179586f / 16000.0f;

    // SC = sqrt(8) / sum_{m=0}^{2047} rho^m
    double rho = exp2(-1.0 / 320.0);
    double geo = (1.0 - exp2(-2048.0 / 320.0)) / (1.0 - rho);
    const float SC = (float)(2.8284271247461903 / geo);

    // d_j = SC * alpha^{-j}, j=1..15 (slot 0 zeroed; cur[0] enters directly)
    float djr[16], dji[16];
    djr[0] = 0.f; dji[0] = 0.f;
#pragma unroll
    for (int j = 1; j < 16; ++j) {
        int ph = (f * j) % SR_I;
        float s, c;
        sincosf(TW * (float)ph, &s, &c);
        float g = SC * exp2f((float)j * (1.0f / 320.0f));   // SC * rho^{-j}
        djr[j] = c * g;
        dji[j] = -s * g;
    }
    unsigned long long dR2[8], dI2[8];
#pragma unroll
    for (int p = 0; p < 8; ++p) {
        dR2[p] = pk2(djr[2 * p], djr[2 * p + 1]);
        dI2[p] = pk2(dji[2 * p], dji[2 * p + 1]);
    }

    // alpha^16
    float A16r, A16i;
    {
        int ph = (16 * f) % SR_I;
        float s, c;
        sincosf(TW * (float)ph, &s, &c);
        float d = exp2f(-16.0f / 320.0f);
        A16r = c * d; A16i = s * d;
    }
    // alpha^2048
    float A2r, A2i;
    {
        int ph = (2048 * f) % SR_I;
        float s, c;
        sincosf(TW * (float)ph, &s, &c);
        float d = exp2f(-2048.0f / 320.0f);
        A2r = c * d; A2i = s * d;
    }

    float rr = 0.f, ri = 0.f, Gr = 0.f, Gi = 0.f;   // rr,ri scaled by SC
    const int t0 = chunk * CHUNK;
    const int clen = (chunk == NCHUNK - 1) ? (TOUT - t0) : CHUNK;

    if (chunk == 0) {
#pragma unroll 8
        for (int i = 0; i < WARM; ++i)
            s_ring[i * BLOCK + tid] = __half2half2(__float2half_rn(0.f));
    } else {
        // 128 warm-up steps: recurrence + ring fill, no output.
        for (int t = t0 - WARM; t < t0; ++t) {
            const ulonglong2* p = (const ulonglong2*)(w + 16 * t);
            ulonglong2 u0 = p[0], u1 = p[1], u2 = p[2], u3 = p[3];
            unsigned long long c2[8] = { u0.x, u0.y, u1.x, u1.y,
                                         u2.x, u2.y, u3.x, u3.y };
            float cur0s = upk2(c2[0]).x * SC;
            float tr = rr + Gr, ti = ri + Gi;
            rr = fmaf(A16r, tr, fmaf(-A16i, ti, cur0s));
            ri = fmaf(A16i, tr, A16r * ti);
            unsigned long long aR = fmul2_(c2[0], dR2[0]);
            unsigned long long aI = fmul2_(c2[0], dI2[0]);
#pragma unroll
            for (int q = 1; q < 8; ++q) {
                aR = ffma2_(c2[q], dR2[q], aR);
                aI = ffma2_(c2[q], dI2[q], aI);
            }
            float2 ar = upk2(aR), ai = upk2(aI);
            Gr = ar.x + ar.y;
            Gi = ai.x + ai.y;
            s_ring[(t & (WARM - 1)) * BLOCK + tid] = __floats2half2_rn(rr, ri);
        }
    }

    float* __restrict__ outs = out + (size_t)gid * TOUT + t0;
    float* __restrict__ outc = out + (size_t)NCHAIN * TOUT + (size_t)gid * TOUT + t0;

    for (int q0 = 0; q0 < clen; q0 += 4) {
        const int tb = t0 + q0;

        // ---- batched prefetch: 4 ring reads + 16 wav LDG.128 ----
        float2 h4[4];
#pragma unroll
        for (int u = 0; u < 4; ++u)
            h4[u] = __half22float2(s_ring[((tb + u) & (WARM - 1)) * BLOCK + tid]);

        ulonglong2 U[4][4];
#pragma unroll
        for (int u = 0; u < 4; ++u) {
            const ulonglong2* p = (const ulonglong2*)(w + 16 * (tb + u));
#pragma unroll
            for (int k = 0; k < 4; ++k) U[u][k] = p[k];
        }

        float obs[4], obc[4];
#pragma unroll
        for (int u = 0; u < 4; ++u) {
            unsigned long long c2[8] = { U[u][0].x, U[u][0].y, U[u][1].x, U[u][1].y,
                                         U[u][2].x, U[u][2].y, U[u][3].x, U[u][3].y };
            float cur0s = upk2(c2[0]).x * SC;
            float tr = rr + Gr, ti = ri + Gi;
            rr = fmaf(A16r, tr, fmaf(-A16i, ti, cur0s));
            ri = fmaf(A16i, tr, A16r * ti);
            unsigned long long aR = fmul2_(c2[0], dR2[0]);
            unsigned long long aI = fmul2_(c2[0], dI2[0]);
#pragma unroll
            for (int q = 1; q < 8; ++q) {
                aR = ffma2_(c2[q], dR2[q], aR);
                aI = ffma2_(c2[q], dI2[q], aI);
            }
            float2 ar = upk2(aR), ai = upk2(aI);
            Gr = ar.x + ar.y;
            Gi = ai.x + ai.y;

            // S = r - alpha^2048 * r[t-128]  (everything pre-scaled by SC)
            float2 h = h4[u];
            s_ring[((tb + u) & (WARM - 1)) * BLOCK + tid] = __floats2half2_rn(rr, ri);
            float Sr = fmaf(-A2r, h.x, fmaf( A2i, h.y, rr));
            float Si = fmaf(-A2i, h.x, fmaf(-A2r, h.y, ri));
            obs[u] = Si;
            obc[u] = Sr;
        }
        *(float4*)(outs + q0) = make_float4(obs[0], obs[1], obs[2], obs[3]);
        *(float4*)(outc + q0) = make_float4(obc[0], obc[1], obc[2], obc[3]);
    }
}

extern "C" void kernel_launch(void* const* d_in, const int* in_sizes, int n_in,
                              void* d_out, int out_size)
{
    (void)in_sizes; (void)n_in; (void)out_size;
    const float* wav = (const float*)d_in[0];   // (2, 32000) fp32
    float* out = (float*)d_out;                 // sspec then cspec, fp32

    static const int smem_bytes = WARM * BLOCK * (int)sizeof(__half2); // 64 KB
    cudaFuncSetAttribute(greentf_kernel,
                         cudaFuncAttributeMaxDynamicSharedMemorySize, smem_bytes);

    dim3 grid((NCHAIN + BLOCK - 1) / BLOCK, NCHUNK, 1);   // 126 x 7 = 882 CTAs
    greentf_kernel<<<grid, BLOCK, smem_bytes>>>(wav, out);
}